// round 12
// baseline (speedup 1.0000x reference)
#include <cuda_runtime.h>
#include <cuda_bf16.h>
#include <cuda_fp16.h>
#include <math.h>
#include <stdint.h>

// ---------------------------------------------------------------------------
// Problem constants
// ---------------------------------------------------------------------------
#define TI_   128
#define NB_   8
#define TO_   32
#define TS_   33
#define D_    512
#define H_    8
#define HD_   64
#define FF_   2048
#define V_    2000
#define VP_   2048
#define L_    6
#define TOK_  (TS_ * NB_)          // 264
#define MJ_   (NB_ * TI_ * TS_)    // 33792
#define FF1_SPLIT 4
#define FF2_SPLIT 16
#define QKV_SPLIT 4
#define O_SPLIT   8
#define NCTA  148

// ---------------------------------------------------------------------------
// Scratch
// ---------------------------------------------------------------------------
__device__ float g_x[TOK_ * D_];
__device__ float g_qkv[QKV_SPLIT * TOK_ * 3 * D_];
__device__ float g_tmp[FF2_SPLIT * TOK_ * D_];
__device__ float g_ftmp[FF1_SPLIT * TOK_ * FF_];
__device__ float g_encp[TI_ * NB_ * D_];

__device__ __nv_bfloat16 g_xh[TOK_ * D_],  g_xl[TOK_ * D_];
__device__ __nv_bfloat16 g_ath[TOK_ * D_], g_atl[TOK_ * D_];
__device__ __nv_bfloat16 g_fh[TOK_ * FF_], g_fl[TOK_ * FF_];

__device__ __nv_bfloat16 g_qkvwh[(size_t)L_ * 3 * D_ * D_], g_qkvwl[(size_t)L_ * 3 * D_ * D_];
__device__ __nv_bfloat16 g_owh[(size_t)L_ * D_ * D_],       g_owl[(size_t)L_ * D_ * D_];
__device__ __nv_bfloat16 g_f1h[(size_t)L_ * FF_ * D_],      g_f1l[(size_t)L_ * FF_ * D_];
__device__ __nv_bfloat16 g_f2h[(size_t)L_ * D_ * FF_],      g_f2l[(size_t)L_ * D_ * FF_];
__device__ __nv_bfloat16 g_ewh[D_ * D_],                    g_ewl[D_ * D_];
__device__ __nv_bfloat16 g_exh[TI_ * NB_ * D_],             g_exl[TI_ * NB_ * D_];

__device__ __half g_Aj[(size_t)MJ_ * D_];
__device__ __half g_Wj[(size_t)VP_ * D_];

// grid barrier state
__device__ unsigned g_bar_count = 0;
__device__ unsigned g_bar_gen   = 0;

// ---------------------------------------------------------------------------
// PTX helpers
// ---------------------------------------------------------------------------
__device__ __forceinline__ uint32_t smem_to_u32(const void* smem_ptr) {
    uint32_t addr;
    asm("{ .reg .u64 tmp; cvta.to.shared.u64 tmp, %1; cvt.u32.u64 %0, tmp; }"
        : "=r"(addr) : "l"(smem_ptr));
    return addr;
}
__device__ __forceinline__ uint32_t sw_off(uint32_t bo) {
    return bo ^ ((bo >> 3) & 0x70);
}
__device__ __forceinline__ void cp_async16(uint32_t saddr, const void* gptr, int valid) {
    asm volatile("cp.async.cg.shared.global [%0], [%1], 16, %2;"
        :: "r"(saddr), "l"(gptr), "r"(valid ? 16 : 0));
}
__device__ __forceinline__ void cp_async_commit() {
    asm volatile("cp.async.commit_group;");
}
template <int N>
__device__ __forceinline__ void cp_async_wait() {
    asm volatile("cp.async.wait_group %0;" :: "n"(N) : "memory");
}
__device__ __forceinline__ void stg_cs_f2(float* p, float a, float b) {
    asm volatile("st.global.cs.v2.f32 [%0], {%1,%2};" :: "l"(p), "f"(a), "f"(b) : "memory");
}

__device__ __forceinline__ void grid_bar() {
    __syncthreads();
    if (threadIdx.x == 0) {
        volatile unsigned* vgen = &g_bar_gen;
        unsigned gen = *vgen;
        __threadfence();
        if (atomicAdd(&g_bar_count, 1u) == NCTA - 1) {
            g_bar_count = 0;
            __threadfence();
            atomicAdd(&g_bar_gen, 1u);
        } else {
            while (*vgen == gen) { __nanosleep(64); }
        }
        __threadfence();
    }
    __syncthreads();
}

// ---------------------------------------------------------------------------
// mma.sync helpers
// ---------------------------------------------------------------------------
__device__ __forceinline__ void ldmatrix_x4(uint32_t* r, uint32_t addr) {
    asm volatile("ldmatrix.sync.aligned.m8n8.x4.shared.b16 {%0,%1,%2,%3}, [%4];"
        : "=r"(r[0]), "=r"(r[1]), "=r"(r[2]), "=r"(r[3]) : "r"(addr));
}
__device__ __forceinline__ void mma16816(float* d, const uint32_t* a,
                                         uint32_t b0, uint32_t b1) {
    asm volatile(
        "mma.sync.aligned.m16n8k16.row.col.f32.bf16.bf16.f32 "
        "{%0,%1,%2,%3}, {%4,%5,%6,%7}, {%8,%9}, {%0,%1,%2,%3};"
        : "+f"(d[0]), "+f"(d[1]), "+f"(d[2]), "+f"(d[3])
        : "r"(a[0]), "r"(a[1]), "r"(a[2]), "r"(a[3]), "r"(b0), "r"(b1));
}
__device__ __forceinline__ void mma16816_f16(float* d, const uint32_t* a,
                                             uint32_t b0, uint32_t b1) {
    asm volatile(
        "mma.sync.aligned.m16n8k16.row.col.f32.f16.f16.f32 "
        "{%0,%1,%2,%3}, {%4,%5,%6,%7}, {%8,%9}, {%0,%1,%2,%3};"
        : "+f"(d[0]), "+f"(d[1]), "+f"(d[2]), "+f"(d[3])
        : "r"(a[0]), "r"(a[1]), "r"(a[2]), "r"(a[3]), "r"(b0), "r"(b1));
}

__device__ __forceinline__ void split_hl(float v, __nv_bfloat16& h, __nv_bfloat16& l) {
    h = __float2bfloat16(v);
    l = __float2bfloat16(v - __bfloat162float(h));
}

// ---------------------------------------------------------------------------
// Fused weight split
// ---------------------------------------------------------------------------
#define NSPLITJOBS 6
struct SplitJobs {
    const float* src[NSPLITJOBS];
    __nv_bfloat16* h[NSPLITJOBS];
    __nv_bfloat16* l[NSPLITJOBS];
    int end[NSPLITJOBS];
};

__global__ void split_all_kernel(SplitJobs jobs, int total) {
    int i = blockIdx.x * blockDim.x + threadIdx.x;
    if (i >= total) return;
    int j = 0;
#pragma unroll
    for (int k = 0; k < NSPLITJOBS - 1; k++) j += (i >= jobs.end[k]);
    int base = (j == 0) ? 0 : jobs.end[j - 1];
    int li = i - base;
    float4 w = ((const float4*)jobs.src[j])[li];
    __nv_bfloat16 h0, h1, h2, h3, l0, l1, l2, l3;
    split_hl(w.x, h0, l0); split_hl(w.y, h1, l1);
    split_hl(w.z, h2, l2); split_hl(w.w, h3, l3);
    ((__nv_bfloat162*)jobs.h[j])[2 * li]     = __nv_bfloat162(h0, h1);
    ((__nv_bfloat162*)jobs.h[j])[2 * li + 1] = __nv_bfloat162(h2, h3);
    ((__nv_bfloat162*)jobs.l[j])[2 * li]     = __nv_bfloat162(l0, l1);
    ((__nv_bfloat162*)jobs.l[j])[2 * li + 1] = __nv_bfloat162(l2, l3);
}

__global__ void w_split_kernel(const float* __restrict__ W,
                               __half* __restrict__ Wj) {
    int r = blockIdx.x;
    int tid = threadIdx.x;
    size_t base = (size_t)r * D_ + tid * 4;
    if (r < V_) {
        const float4 w = ((const float4*)(W + (size_t)r * D_))[tid];
        ((__half2*)(Wj + base))[0] = __half2(__float2half(w.x), __float2half(w.y));
        ((__half2*)(Wj + base))[1] = __half2(__float2half(w.z), __float2half(w.w));
    } else {
        __half2 z = __half2(__float2half(0.f), __float2half(0.f));
        ((__half2*)(Wj + base))[0] = z;
        ((__half2*)(Wj + base))[1] = z;
    }
}

// ---------------------------------------------------------------------------
// Embedding + positions
// ---------------------------------------------------------------------------
__global__ void embed_kernel(const float* __restrict__ embed,
                             const int* __restrict__ tgt_pad,
                             const int* __restrict__ sos,
                             float* __restrict__ x,
                             __nv_bfloat16* __restrict__ xh,
                             __nv_bfloat16* __restrict__ xl) {
    int r = blockIdx.x;
    int t = r >> 3, n = r & 7;
    int tok = (t == 0) ? sos[0] : tgt_pad[n * TO_ + (t - 1)];
    const float* e = embed + (size_t)tok * D_;
    const float sc = sqrtf(512.0f);
    int tid = threadIdx.x;
#pragma unroll
    for (int i = 0; i < 2; i++) {
        int d = tid * 4 + i * 2;
        float ddiv = expf((float)d * (-9.210340371976184f / 512.0f));
        float ang = (float)t * ddiv;
        float sv, cv;
        sincosf(ang, &sv, &cv);
        size_t idx = (size_t)r * D_ + d;
        float v0 = e[d] * sc + sv;
        float v1 = e[d + 1] * sc + cv;
        x[idx] = v0; x[idx + 1] = v1;
        __nv_bfloat16 h0, l0, h1, l1;
        split_hl(v0, h0, l0); split_hl(v1, h1, l1);
        xh[idx] = h0; xh[idx + 1] = h1;
        xl[idx] = l0; xl[idx + 1] = l1;
    }
}

// ---------------------------------------------------------------------------
// Tile loaders + mainloops (shared)
// ---------------------------------------------------------------------------
__device__ __forceinline__ void tc_load_half_async(const __nv_bfloat16* __restrict__ src,
                                                   int row0, int maxrow, int kelem,
                                                   int kstride, uint32_t sm, int tid, int p) {
#pragma unroll
    for (int q = 0; q < 2; q++) {
        int idx = q * 256 + tid;
        int row = idx >> 2, seg = idx & 3;
        int gr = row0 + row;
        uint32_t bo = (uint32_t)(row * 128 + p * 64 + seg * 16);
        cp_async16(sm + sw_off(bo),
                   src + (size_t)gr * kstride + kelem + seg * 8,
                   gr < maxrow);
    }
}

#define JT_BUF      16384
#define JT_SM_AH    1024
#define JT_SM_AL    (JT_SM_AH + JT_BUF)
#define JT_SM_WH    (JT_SM_AL + JT_BUF)
#define JT_SM_WL    (JT_SM_WH + JT_BUF)
#define JT_SMEM     (JT_SM_WL + JT_BUF)      // 66560

#define JJ_SM_A     1024
#define JJ_SM_W     (JJ_SM_A + JT_BUF)
#define JJ_SMEM     (JJ_SM_W + JT_BUF)       // 33792

__device__ __forceinline__ void load_half4(const __nv_bfloat16* Ah, const __nv_bfloat16* Al,
                                           const __nv_bfloat16* Wh, const __nv_bfloat16* Wl,
                                           int m0, int M, int n0, int N,
                                           int kelem, int kstride,
                                           uint32_t sbase, int tid, int p) {
    tc_load_half_async(Ah, m0, M, kelem, kstride, sbase + JT_SM_AH, tid, p);
    tc_load_half_async(Al, m0, M, kelem, kstride, sbase + JT_SM_AL, tid, p);
    tc_load_half_async(Wh, n0, N, kelem, kstride, sbase + JT_SM_WH, tid, p);
    tc_load_half_async(Wl, n0, N, kelem, kstride, sbase + JT_SM_WL, tid, p);
}
__device__ __forceinline__ void load_half2_j(const __half* A, const __half* W,
                                             int m0, int n0, int kelem,
                                             uint32_t sbase, int tid, int p) {
    tc_load_half_async((const __nv_bfloat16*)A, m0, MJ_, kelem, D_, sbase + JJ_SM_A, tid, p);
    tc_load_half_async((const __nv_bfloat16*)W, n0, VP_, kelem, D_, sbase + JJ_SM_W, tid, p);
}

__device__ __forceinline__ void mma_mainloop_half(uint32_t sbase, int wr, int wc,
                                                  int lane, float acc[16][4], int p) {
    const int boffs[3] = {JT_SM_WH, JT_SM_WL, JT_SM_WH};
    const int bt = lane >> 3, br_ = lane & 7;
#pragma unroll
    for (int si = 0; si < 2; si++) {
        const int s = 2 * p + si;
        uint32_t AH[2][4], AL[2][4];
#pragma unroll
        for (int mi = 0; mi < 2; mi++) {
            uint32_t bo = (uint32_t)((wr * 32 + mi * 16 + (lane & 15)) * 128
                                     + s * 32 + (lane >> 4) * 16);
            ldmatrix_x4(AH[mi], sbase + JT_SM_AH + sw_off(bo));
            ldmatrix_x4(AL[mi], sbase + JT_SM_AL + sw_off(bo));
        }
#pragma unroll
        for (int tm = 0; tm < 3; tm++) {
            const uint32_t (*af)[4] = (tm == 2) ? AL : AH;
#pragma unroll
            for (int g = 0; g < 4; g++) {
                uint32_t bo = (uint32_t)((wc * 64 + g * 16 + (bt >> 1) * 8 + br_) * 128
                                         + s * 32 + (bt & 1) * 16);
                uint32_t bfr[4];
                ldmatrix_x4(bfr, sbase + boffs[tm] + sw_off(bo));
                mma16816(acc[2 * g],     af[0], bfr[0], bfr[1]);
                mma16816(acc[8 + 2 * g], af[1], bfr[0], bfr[1]);
                mma16816(acc[2 * g + 1],     af[0], bfr[2], bfr[3]);
                mma16816(acc[8 + 2 * g + 1], af[1], bfr[2], bfr[3]);
            }
        }
    }
}
__device__ __forceinline__ void mma_mainloop_half_j(uint32_t sbase, int wr, int wc,
                                                    int lane, float acc[16][4], int p) {
    const int bt = lane >> 3, br_ = lane & 7;
#pragma unroll
    for (int si = 0; si < 2; si++) {
        const int s = 2 * p + si;
        uint32_t afrag[2][4];
#pragma unroll
        for (int mi = 0; mi < 2; mi++) {
            uint32_t bo = (uint32_t)((wr * 32 + mi * 16 + (lane & 15)) * 128
                                     + s * 32 + (lane >> 4) * 16);
            ldmatrix_x4(afrag[mi], sbase + JJ_SM_A + sw_off(bo));
        }
#pragma unroll
        for (int g = 0; g < 4; g++) {
            uint32_t bo = (uint32_t)((wc * 64 + g * 16 + (bt >> 1) * 8 + br_) * 128
                                     + s * 32 + (bt & 1) * 16);
            uint32_t bfr[4];
            ldmatrix_x4(bfr, sbase + JJ_SM_W + sw_off(bo));
            mma16816_f16(acc[2 * g],     afrag[0], bfr[0], bfr[1]);
            mma16816_f16(acc[8 + 2 * g], afrag[1], bfr[0], bfr[1]);
            mma16816_f16(acc[2 * g + 1],     afrag[0], bfr[2], bfr[3]);
            mma16816_f16(acc[8 + 2 * g + 1], afrag[1], bfr[2], bfr[3]);
        }
    }
}

// ---------------------------------------------------------------------------
// GEMM tile body (device): one 128x128 tile with z chunk-range, fp32 C out
// ---------------------------------------------------------------------------
__device__ __forceinline__ void gemm_tile(
    const __nv_bfloat16* Ah, const __nv_bfloat16* Al,
    const __nv_bfloat16* Wh, const __nv_bfloat16* Wl,
    const float* bias, float* C,
    int M, int N, int kstride, int chunks, int koff0, int addb,
    uint32_t sbase, int tid, int m0, int n0) {
    const int w = tid >> 5, lane = tid & 31;
    const int wr = w >> 1, wc = w & 1;

    float acc[16][4];
#pragma unroll
    for (int i = 0; i < 16; i++)
#pragma unroll
        for (int j = 0; j < 4; j++) acc[i][j] = 0.f;

    const int nhalf = chunks * 2;
    load_half4(Ah, Al, Wh, Wl, m0, M, n0, N, koff0, kstride, sbase, tid, 0);
    cp_async_commit();
    for (int c = 0; c < nhalf; c++) {
        if (c + 1 < nhalf) {
            load_half4(Ah, Al, Wh, Wl, m0, M, n0, N,
                       koff0 + (c + 1) * 32, kstride, sbase, tid, (c + 1) & 1);
            cp_async_commit();
            cp_async_wait<1>();
        } else {
            cp_async_wait<0>();
        }
        __syncthreads();
        mma_mainloop_half(sbase, wr, wc, lane, acc, c & 1);
        __syncthreads();
    }

#pragma unroll
    for (int mi = 0; mi < 2; mi++) {
#pragma unroll
        for (int nt = 0; nt < 8; nt++) {
            int m = m0 + wr * 32 + mi * 16 + (lane >> 2);
            int ncol = n0 + wc * 64 + nt * 8 + 2 * (lane & 3);
            float b0v = addb ? bias[ncol] : 0.f;
            float b1v = addb ? bias[ncol + 1] : 0.f;
            if (m < M)
                *(float2*)(C + (size_t)m * N + ncol) =
                    make_float2(acc[mi * 8 + nt][0] + b0v, acc[mi * 8 + nt][1] + b1v);
            if (m + 8 < M)
                *(float2*)(C + (size_t)(m + 8) * N + ncol) =
                    make_float2(acc[mi * 8 + nt][2] + b0v, acc[mi * 8 + nt][3] + b1v);
        }
    }
}

// job-strided gemm stage
__device__ __forceinline__ void stage_gemm(
    const __nv_bfloat16* Ah, const __nv_bfloat16* Al,
    const __nv_bfloat16* Wh, const __nv_bfloat16* Wl,
    const float* bias, float* Cbase,
    int M, int N, int kstride, int chunks, int zsplit,
    uint32_t sbase, int tid) {
    const int ntiles = N >> 7;
    const int mtiles = (M + 127) >> 7;
    const int njobs = ntiles * mtiles * zsplit;
    for (int job = blockIdx.x; job < njobs; job += NCTA) {
        int nt = job % ntiles;
        int rj = job / ntiles;
        int mt = rj % mtiles;
        int z  = rj / mtiles;
        gemm_tile(Ah, Al, Wh, Wl, bias, Cbase + (size_t)z * M * N,
                  M, N, kstride, chunks, z * chunks * 64,
                  (bias != nullptr) && (z == 0), sbase, tid, mt * 128, nt * 128);
    }
}

// ---------------------------------------------------------------------------
// Attention stage (device)
// ---------------------------------------------------------------------------
__device__ __forceinline__ void stage_attn(const float* qkv, const int* tgt_len,
                                           __nv_bfloat16* oh, __nv_bfloat16* ol,
                                           char* smem) {
    float* qs = (float*)smem;
    float* ks = qs + TS_ * HD_;
    float* vs = ks + TS_ * HD_;
    float* sc = vs + TS_ * HD_;   // TS_ x (TS_+1)
    int tid = threadIdx.x;
    for (int job = blockIdx.x; job < NB_ * H_; job += NCTA) {
        int n = job >> 3, h = job & 7;
        int len = tgt_len[n]; if (len < 1) len = 1;

        for (int e = tid; e < TS_ * HD_; e += 256) {
            int t = e >> 6, d = e & 63;
            size_t off = (size_t)(t * 8 + n) * (3 * D_) + h * 64 + d;
            float q = 0.f, k = 0.f, v = 0.f;
#pragma unroll
            for (int z = 0; z < QKV_SPLIT; z++) {
                const float* b = qkv + (size_t)z * TOK_ * 3 * D_ + off;
                q += b[0]; k += b[512]; v += b[1024];
            }
            qs[t * HD_ + d] = q; ks[t * HD_ + d] = k; vs[t * HD_ + d] = v;
        }
        __syncthreads();

        for (int p = tid; p < TS_ * TS_; p += 256) {
            int tq = p / TS_, tk = p - tq * TS_;
            float s;
            if (tk > tq || tk >= len) {
                s = -1e9f;
            } else {
                const float4* q4 = (const float4*)(qs + tq * HD_);
                const float4* k4 = (const float4*)(ks + tk * HD_);
                float s0 = 0.f, s1 = 0.f, s2 = 0.f, s3 = 0.f;
#pragma unroll
                for (int d = 0; d < HD_ / 4; d += 2) {
                    float4 qa = q4[d], ka = k4[d];
                    float4 qb = q4[d + 1], kb = k4[d + 1];
                    s0 += qa.x * ka.x + qa.y * ka.y;
                    s1 += qa.z * ka.z + qa.w * ka.w;
                    s2 += qb.x * kb.x + qb.y * kb.y;
                    s3 += qb.z * kb.z + qb.w * kb.w;
                }
                s = ((s0 + s1) + (s2 + s3)) * 0.125f;
            }
            sc[tq * (TS_ + 1) + tk] = s;
        }
        __syncthreads();

        {
            int w = tid >> 5, lane = tid & 31;
            for (int tq = w; tq < TS_; tq += 8) {
                float v0 = sc[tq * (TS_ + 1) + lane];
                float v1 = (lane == 0) ? sc[tq * (TS_ + 1) + 32] : -1e30f;
                float mx = fmaxf(v0, v1);
#pragma unroll
                for (int off = 16; off > 0; off >>= 1)
                    mx = fmaxf(mx, __shfl_xor_sync(0xffffffffu, mx, off));
                float e0 = expf(v0 - mx);
                float e1 = (lane == 0) ? expf(v1 - mx) : 0.f;
                float sum = e0 + e1;
#pragma unroll
                for (int off = 16; off > 0; off >>= 1)
                    sum += __shfl_xor_sync(0xffffffffu, sum, off);
                float inv = 1.0f / sum;
                sc[tq * (TS_ + 1) + lane] = e0 * inv;
                if (lane == 0) sc[tq * (TS_ + 1) + 32] = e1 * inv;
            }
        }
        __syncthreads();

        for (int e = tid; e < TS_ * HD_; e += 256) {
            int tq = e >> 6, d = e & 63;
            float s = 0.f;
#pragma unroll 11
            for (int tk = 0; tk < TS_; tk++)
                s += sc[tq * (TS_ + 1) + tk] * vs[tk * HD_ + d];
            size_t idx = (size_t)(tq * 8 + n) * D_ + h * 64 + d;
            __nv_bfloat16 hv, lv;
            split_hl(s, hv, lv);
            oh[idx] = hv; ol[idx] = lv;
        }
        __syncthreads();
    }
}

// ---------------------------------------------------------------------------
// Add + LN stage (device, 256 threads per row, 2 floats/thread)
// ---------------------------------------------------------------------------
__device__ __forceinline__ void stage_add_ln(float* x, const float* y, int nsplit,
                                             const float* s, const float* b,
                                             __nv_bfloat16* xh, __nv_bfloat16* xl,
                                             char* smem) {
    float* sh = (float*)smem;   // 16 floats
    int tid = threadIdx.x, lane = tid & 31, w = tid >> 5;
    for (int row = blockIdx.x; row < TOK_; row += NCTA) {
        float2 xv = ((const float2*)(x + (size_t)row * D_))[tid];
        float r0 = xv.x, r1 = xv.y;
        for (int z = 0; z < nsplit; z++) {
            float2 yv = ((const float2*)(y + (size_t)z * TOK_ * D_ + (size_t)row * D_))[tid];
            r0 += yv.x; r1 += yv.y;
        }
        float sum = r0 + r1;
#pragma unroll
        for (int off = 16; off > 0; off >>= 1)
            sum += __shfl_xor_sync(0xffffffffu, sum, off);
        if (lane == 0) sh[w] = sum;
        __syncthreads();
        float mean = 0.f;
#pragma unroll
        for (int i = 0; i < 8; i++) mean += sh[i];
        mean *= (1.0f / 512.0f);

        float d0 = r0 - mean, d1 = r1 - mean;
        float sq = d0 * d0 + d1 * d1;
#pragma unroll
        for (int off = 16; off > 0; off >>= 1)
            sq += __shfl_xor_sync(0xffffffffu, sq, off);
        if (lane == 0) sh[8 + w] = sq;
        __syncthreads();
        float var = 0.f;
#pragma unroll
        for (int i = 0; i < 8; i++) var += sh[8 + i];
        var *= (1.0f / 512.0f);
        float rstd = 1.0f / sqrtf(var + 1e-5f);

        float2 sv = ((const float2*)s)[tid];
        float2 bv = ((const float2*)b)[tid];
        float o0 = d0 * rstd * sv.x + bv.x;
        float o1 = d1 * rstd * sv.y + bv.y;
        ((float2*)(x + (size_t)row * D_))[tid] = make_float2(o0, o1);

        size_t base = (size_t)row * D_ + tid * 2;
        __nv_bfloat16 h0, h1, l0, l1;
        split_hl(o0, h0, l0); split_hl(o1, h1, l1);
        *(__nv_bfloat162*)(xh + base) = __nv_bfloat162(h0, h1);
        *(__nv_bfloat162*)(xl + base) = __nv_bfloat162(l0, l1);
        __syncthreads();
    }
}

// ---------------------------------------------------------------------------
// FF1 finalize stage (device)
// ---------------------------------------------------------------------------
__device__ __forceinline__ void stage_relu(const float* ft, const float* bias,
                                           __nv_bfloat16* fh, __nv_bfloat16* fl) {
    const int total = TOK_ * FF_ / 4;
    for (int i = blockIdx.x * 256 + threadIdx.x; i < total; i += NCTA * 256) {
        float4 s = ((const float4*)ft)[i];
#pragma unroll
        for (int z = 1; z < FF1_SPLIT; z++) {
            float4 v = ((const float4*)(ft + (size_t)z * TOK_ * FF_))[i];
            s.x += v.x; s.y += v.y; s.z += v.z; s.w += v.w;
        }
        float4 b = ((const float4*)bias)[i & (FF_ / 4 - 1)];
        float v0 = fmaxf(s.x + b.x, 0.f);
        float v1 = fmaxf(s.y + b.y, 0.f);
        float v2 = fmaxf(s.z + b.z, 0.f);
        float v3 = fmaxf(s.w + b.w, 0.f);
        __nv_bfloat16 h0, h1, h2, h3, l0, l1, l2, l3;
        split_hl(v0, h0, l0); split_hl(v1, h1, l1);
        split_hl(v2, h2, l2); split_hl(v3, h3, l3);
        ((__nv_bfloat162*)fh)[2 * i]     = __nv_bfloat162(h0, h1);
        ((__nv_bfloat162*)fh)[2 * i + 1] = __nv_bfloat162(h2, h3);
        ((__nv_bfloat162*)fl)[2 * i]     = __nv_bfloat162(l0, l1);
        ((__nv_bfloat162*)fl)[2 * i + 1] = __nv_bfloat162(l2, l3);
    }
}

// ---------------------------------------------------------------------------
// Persistent fused layer-chain kernel (one launch for all 6 layers)
// ---------------------------------------------------------------------------
struct ChainParams {
    const __nv_bfloat16 *qkvwh, *qkvwl, *owh, *owl, *f1h, *f1l, *f2h, *f2l;
    const float *qkv_b, *o_b, *ff1_b, *ff2_b, *ln1_s, *ln1_b, *ln2_s, *ln2_b;
    const int* tgt_len;
    float *x, *qkv, *tmp, *ftmp;
    __nv_bfloat16 *xh, *xl, *ath, *atl, *fh, *fl;
};

__global__ void __launch_bounds__(256) chain_kernel(ChainParams P) {
    extern __shared__ char smem[];
    const uint32_t sbase = smem_to_u32(smem);
    const int tid = threadIdx.x;

    for (int l = 0; l < L_; l++) {
        stage_gemm(P.xh, P.xl,
                   P.qkvwh + (size_t)l * 3 * D_ * D_, P.qkvwl + (size_t)l * 3 * D_ * D_,
                   P.qkv_b + (size_t)l * 3 * D_, P.qkv,
                   TOK_, 3 * D_, D_, 8 / QKV_SPLIT, QKV_SPLIT, sbase, tid);
        grid_bar();
        stage_attn(P.qkv, P.tgt_len, P.ath, P.atl, smem);
        grid_bar();
        stage_gemm(P.ath, P.atl,
                   P.owh + (size_t)l * D_ * D_, P.owl + (size_t)l * D_ * D_,
                   P.o_b + (size_t)l * D_, P.tmp,
                   TOK_, D_, D_, 8 / O_SPLIT, O_SPLIT, sbase, tid);
        grid_bar();
        stage_add_ln(P.x, P.tmp, O_SPLIT,
                     P.ln1_s + (size_t)l * D_, P.ln1_b + (size_t)l * D_,
                     P.xh, P.xl, smem);
        grid_bar();
        stage_gemm(P.xh, P.xl,
                   P.f1h + (size_t)l * FF_ * D_, P.f1l + (size_t)l * FF_ * D_,
                   nullptr, P.ftmp,
                   TOK_, FF_, D_, 8 / FF1_SPLIT, FF1_SPLIT, sbase, tid);
        grid_bar();
        stage_relu(P.ftmp, P.ff1_b + (size_t)l * FF_, P.fh, P.fl);
        grid_bar();
        stage_gemm(P.fh, P.fl,
                   P.f2h + (size_t)l * D_ * FF_, P.f2l + (size_t)l * D_ * FF_,
                   P.ff2_b + (size_t)l * D_, P.tmp,
                   TOK_, D_, FF_, 32 / FF2_SPLIT, FF2_SPLIT, sbase, tid);
        grid_bar();
        stage_add_ln(P.x, P.tmp, FF2_SPLIT,
                     P.ln2_s + (size_t)l * D_, P.ln2_b + (size_t)l * D_,
                     P.xh, P.xl, smem);
        grid_bar();
    }
}

// ---------------------------------------------------------------------------
// Standalone GEMM kernel (enc projection only)
// ---------------------------------------------------------------------------
__global__ void __launch_bounds__(256) gemm_tc(
    const __nv_bfloat16* __restrict__ Ah, const __nv_bfloat16* __restrict__ Al,
    const __nv_bfloat16* __restrict__ Wh, const __nv_bfloat16* __restrict__ Wl,
    const float* __restrict__ bias, float* __restrict__ C,
    int M, int N, int kstride, int chunks) {
    extern __shared__ char smem[];
    const uint32_t sbase = smem_to_u32(smem);
    gemm_tile(Ah, Al, Wh, Wl, bias, C, M, N, kstride, chunks, 0,
              bias != nullptr, sbase, threadIdx.x,
              blockIdx.y * 128, blockIdx.x * 128);
}

// ---------------------------------------------------------------------------
// Joiner A materialization -> single fp16
// ---------------------------------------------------------------------------
__global__ void joiner_a_kernel(const float* __restrict__ enc,
                                const float* __restrict__ x,
                                __half* __restrict__ A) {
    int r = blockIdx.x;
    int n = r / (TI_ * TS_);
    int rem = r - n * (TI_ * TS_);
    int i = rem / TS_;
    int t = rem - i * TS_;
    const float4* er = (const float4*)(enc + (size_t)(i * 8 + n) * D_);
    const float4* xr = (const float4*)(x + (size_t)(t * 8 + n) * D_);
    int tid = threadIdx.x;
    float4 e = er[tid], xx = xr[tid];
    __half2 h0 = __half2(__float2half(tanhf(e.x + xx.x)), __float2half(tanhf(e.y + xx.y)));
    __half2 h1 = __half2(__float2half(tanhf(e.z + xx.z)), __float2half(tanhf(e.w + xx.w)));
    size_t base = (size_t)r * D_ + tid * 4;
    ((__half2*)(A + base))[0] = h0;
    ((__half2*)(A + base))[1] = h1;
}

// ---------------------------------------------------------------------------
// Joiner GEMM (tile 128x128, K=512, plain fp16, mma.sync)
// ---------------------------------------------------------------------------
#define JT_CHUNKS   8

__global__ void __launch_bounds__(256) joiner_tc_kernel(
    const __half* __restrict__ A,
    const __half* __restrict__ W,
    float* __restrict__ C) {
    extern __shared__ char smem[];
    const uint32_t sbase = smem_to_u32(smem);
    const int tid = threadIdx.x;
    const int n0 = blockIdx.x * 128;
    const int m0 = blockIdx.y * 128;

    const int w = tid >> 5, lane = tid & 31;
    const int wr = w >> 1, wc = w & 1;

    float acc[16][4];
#pragma unroll
    for (int i = 0; i < 16; i++)
#pragma unroll
        for (int j = 0; j < 4; j++) acc[i][j] = 0.f;

    const int nhalf = JT_CHUNKS * 2;
    load_half2_j(A, W, m0, n0, 0, sbase, tid, 0);
    cp_async_commit();
    for (int c = 0; c < nhalf; c++) {
        if (c + 1 < nhalf) {
            load_half2_j(A, W, m0, n0, (c + 1) * 32, sbase, tid, (c + 1) & 1);
            cp_async_commit();
            cp_async_wait<1>();
        } else {
            cp_async_wait<0>();
        }
        __syncthreads();
        mma_mainloop_half_j(sbase, wr, wc, lane, acc, c & 1);
        __syncthreads();
    }

#pragma unroll
    for (int mi = 0; mi < 2; mi++) {
#pragma unroll
        for (int nt = 0; nt < 8; nt++) {
            int m = m0 + wr * 32 + mi * 16 + (lane >> 2);
            int ncol = n0 + wc * 64 + nt * 8 + 2 * (lane & 3);
            if (ncol < V_) {
                stg_cs_f2(C + (size_t)m * V_ + ncol,
                          acc[mi * 8 + nt][0], acc[mi * 8 + nt][1]);
                stg_cs_f2(C + (size_t)(m + 8) * V_ + ncol,
                          acc[mi * 8 + nt][2], acc[mi * 8 + nt][3]);
            }
        }
    }
}

// ---------------------------------------------------------------------------
// Host orchestration
// ---------------------------------------------------------------------------
extern "C" void kernel_launch(void* const* d_in, const int* in_sizes, int n_in,
                              void* d_out, int out_size) {
    const float* enc_out = (const float*)d_in[0];
    const float* embed_w = (const float*)d_in[1];
    const float* enc_w   = (const float*)d_in[2];
    const float* enc_b   = (const float*)d_in[3];
    const float* qkv_w   = (const float*)d_in[4];
    const float* qkv_b   = (const float*)d_in[5];
    const float* o_w     = (const float*)d_in[6];
    const float* o_b     = (const float*)d_in[7];
    const float* ln1_s   = (const float*)d_in[8];
    const float* ln1_b   = (const float*)d_in[9];
    const float* ff1_w   = (const float*)d_in[10];
    const float* ff1_b   = (const float*)d_in[11];
    const float* ff2_w   = (const float*)d_in[12];
    const float* ff2_b   = (const float*)d_in[13];
    const float* ln2_s   = (const float*)d_in[14];
    const float* ln2_b   = (const float*)d_in[15];
    const float* out_w   = (const float*)d_in[16];
    const int*   tgt_pad = (const int*)d_in[17];
    const int*   tgt_len = (const int*)d_in[18];
    const int*   sos     = (const int*)d_in[19];

    float *x, *qkv, *tmp, *ftmp, *encp;
    cudaGetSymbolAddress((void**)&x, g_x);
    cudaGetSymbolAddress((void**)&qkv, g_qkv);
    cudaGetSymbolAddress((void**)&tmp, g_tmp);
    cudaGetSymbolAddress((void**)&ftmp, g_ftmp);
    cudaGetSymbolAddress((void**)&encp, g_encp);

    __nv_bfloat16 *xh, *xl, *ath, *atl, *fh, *fl;
    cudaGetSymbolAddress((void**)&xh, g_xh);
    cudaGetSymbolAddress((void**)&xl, g_xl);
    cudaGetSymbolAddress((void**)&ath, g_ath);
    cudaGetSymbolAddress((void**)&atl, g_atl);
    cudaGetSymbolAddress((void**)&fh, g_fh);
    cudaGetSymbolAddress((void**)&fl, g_fl);

    __nv_bfloat16 *qkvwh, *qkvwl, *owh, *owl, *f1h, *f1l, *f2h, *f2l, *ewh, *ewl, *exh, *exl;
    cudaGetSymbolAddress((void**)&qkvwh, g_qkvwh);
    cudaGetSymbolAddress((void**)&qkvwl, g_qkvwl);
    cudaGetSymbolAddress((void**)&owh, g_owh);
    cudaGetSymbolAddress((void**)&owl, g_owl);
    cudaGetSymbolAddress((void**)&f1h, g_f1h);
    cudaGetSymbolAddress((void**)&f1l, g_f1l);
    cudaGetSymbolAddress((void**)&f2h, g_f2h);
    cudaGetSymbolAddress((void**)&f2l, g_f2l);
    cudaGetSymbolAddress((void**)&ewh, g_ewh);
    cudaGetSymbolAddress((void**)&ewl, g_ewl);
    cudaGetSymbolAddress((void**)&exh, g_exh);
    cudaGetSymbolAddress((void**)&exl, g_exl);

    __half *Aj, *Wj;
    cudaGetSymbolAddress((void**)&Aj, g_Aj);
    cudaGetSymbolAddress((void**)&Wj, g_Wj);

    static bool attr_done = false;
    if (!attr_done) {
        cudaFuncSetAttribute(joiner_tc_kernel,
                             cudaFuncAttributeMaxDynamicSharedMemorySize, JJ_SMEM);
        cudaFuncSetAttribute(gemm_tc,
                             cudaFuncAttributeMaxDynamicSharedMemorySize, JT_SMEM);
        cudaFuncSetAttribute(chain_kernel,
                             cudaFuncAttributeMaxDynamicSharedMemorySize, JT_SMEM);
        attr_done = true;
    }

    // ---- fused weight splits + padded fp16 out_w ----
    {
        SplitJobs jobs;
        int c0 = L_ * 3 * D_ * D_ / 4;
        int c1 = L_ * D_ * D_ / 4;
        int c2 = L_ * FF_ * D_ / 4;
        int c3 = L_ * D_ * FF_ / 4;
        int c4 = D_ * D_ / 4;
        int c5 = TI_ * NB_ * D_ / 4;
        jobs.src[0] = qkv_w;  jobs.h[0] = qkvwh; jobs.l[0] = qkvwl; jobs.end[0] = c0;
        jobs.src[1] = o_w;    jobs.h[1] = owh;   jobs.l[1] = owl;   jobs.end[1] = jobs.end[0] + c1;
        jobs.src[2] = ff1_w;  jobs.h[2] = f1h;   jobs.l[2] = f1l;   jobs.end[2] = jobs.end[1] + c2;
        jobs.src[3] = ff2_w;  jobs.h[3] = f2h;   jobs.l[3] = f2l;   jobs.end[3] = jobs.end[2] + c3;
        jobs.src[4] = enc_w;  jobs.h[4] = ewh;   jobs.l[4] = ewl;   jobs.end[4] = jobs.end[3] + c4;
        jobs.src[5] = enc_out;jobs.h[5] = exh;   jobs.l[5] = exl;   jobs.end[5] = jobs.end[4] + c5;
        int total = jobs.end[5];
        split_all_kernel<<<(total + 255) / 256, 256>>>(jobs, total);
        w_split_kernel<<<VP_, 128>>>(out_w, Wj);
    }

    // enc projection (1024 x 512 = 32 tiles, one normal launch)
    gemm_tc<<<dim3(D_ / 128, (TI_ * NB_) / 128), 256, JT_SMEM>>>(
        exh, exl, ewh, ewl, enc_b, encp, TI_ * NB_, D_, D_, 8);

    // embedding + positions
    embed_kernel<<<TOK_, 128>>>(embed_w, tgt_pad, sos, x, xh, xl);

    // 6 transformer layers, ONE persistent launch
    {
        ChainParams P;
        P.qkvwh = qkvwh; P.qkvwl = qkvwl; P.owh = owh; P.owl = owl;
        P.f1h = f1h; P.f1l = f1l; P.f2h = f2h; P.f2l = f2l;
        P.qkv_b = qkv_b; P.o_b = o_b; P.ff1_b = ff1_b; P.ff2_b = ff2_b;
        P.ln1_s = ln1_s; P.ln1_b = ln1_b; P.ln2_s = ln2_s; P.ln2_b = ln2_b;
        P.tgt_len = tgt_len;
        P.x = x; P.qkv = qkv; P.tmp = tmp; P.ftmp = ftmp;
        P.xh = xh; P.xl = xl; P.ath = ath; P.atl = atl; P.fh = fh; P.fl = fl;
        chain_kernel<<<NCTA, 256, JT_SMEM>>>(P);
    }

    // joiner
    joiner_a_kernel<<<MJ_, 128>>>(encp, x, Aj);
    joiner_tc_kernel<<<dim3(VP_ / 128, MJ_ / 128), 256, JJ_SMEM>>>(
        Aj, Wj, (float*)d_out);
}